// round 15
// baseline (speedup 1.0000x reference)
#include <cuda_runtime.h>
#include <cstdint>

// SimplePatchScorer: out[b, j] = dot(W, permuted_patch_row(b, j)) + bias
//   x: (512, 3, 224, 224) fp32, W: (1,768), b: (1,) -> out: (512, 196)
//
// flat[u], u = s*588 + v; s = ph*16+pw; v = c*196 + hn*14 + wn.
// out[b,j] = sum_t W[t]*flat[768j+t] + bias.
// lcm(588,768)=37632 => 4 groups/image: s in [64g,64g+64), j in [49g,49g+49).
//
// v13: ROLE-SWAP WARP GROUPS. Two groups of 4 warps; eighth-tiles (8 s'
// rows, u' range [4704t,4704t+4704), parity p = t&1). Group p owns buffer p
// and tiles of parity p: at step s group (t0+s)&1 LOADS its next tile while
// the other group COMPUTES the tile it loaded last step (v9's swizzled
// f32x2 smem-W loop). One __syncthreads per step enforces antiphase ->
// DRAM streams while FMAs run, inside every CTA. Row partials: acc[13]
// per warp (rows jl = 4i + wg), merged via smem atomicAdd at the end.
// ~42 KB smem -> 5 CTAs/SM; 8-way tile stagger across CTAs retained.

#define VPAD    604
#define TILE_U  4704           // 8 * 588
#define THREADS 256

__global__ __launch_bounds__(THREADS, 5)
void patch_scorer_v13(const float* __restrict__ x,
                      const float* __restrict__ W,
                      const float* __restrict__ bias,
                      float* __restrict__ out)
{
    extern __shared__ float smem[];
    float* Ws     = smem + 16 * VPAD;          // [768]
    float* outacc = smem + 16 * VPAD + 768;    // [49]

    const int tid  = threadIdx.x;
    const int g    = blockIdx.x & 3;
    const int b    = blockIdx.x >> 2;
    const int lane = tid & 31;
    const int warp = tid >> 5;        // 8 warps
    const int grp  = warp >> 2;       // 0 or 1
    const int wg   = warp & 3;        // warp-in-group
    const int ltid = tid & 127;       // thread-in-group

    const float* xb = x + (size_t)b * 150528;
    const uint32_t ybase = (uint32_t)__cvta_generic_to_shared(smem);
    const uint32_t wbase = (uint32_t)__cvta_generic_to_shared(Ws);

    if (tid < 192)                    // 192 float4 = 768 floats
        ((float4*)Ws)[tid] = ((const float4*)W)[tid];
    if (tid < 49) outacc[tid] = 0.f;

    float acc[13];
    #pragma unroll
    for (int i = 0; i < 13; i++) acc[i] = 0.f;

    const int t0 = ((blockIdx.x >> 2) * 5) & 7;   // 8-way stagger

    // per-thread phase-1 decode seed (f = ltid): q4 = f%28, r = f/28
    const int q40 = ltid % 28;
    const int r0s = ltid / 28;
    const int hn0 = r0s % 14;
    const int c0  = r0s / 14;

    for (int s = 0; s <= 8; s++) {
        const int tl = (t0 + s) & 7;              // tile loaded this step
        if (grp == (tl & 1)) {
            // ================= LOAD tile tl into buffer grp =============
            if (s < 8) {
                float* Y = smem + grp * (8 * VPAD);
                const float* bp = xb + (4 * g + (tl >> 1)) * 224 + 8 * (tl & 1);
                int q4 = q40, hn = hn0, c = c0;
                #pragma unroll 3
                for (int f = ltid; f < 1176; f += 128) {
                    int wn = q4 >> 1, kk = q4 & 1;
                    float4 val = __ldcs((const float4*)(bp +
                        c * 50176 + hn * 3584 + wn * 16 + 4 * kk));
                    int col  = c * 196 + hn * 14 + wn;
                    int xcol = (((col >> 2) ^ kk) << 2) | (col & 3);
                    float* dst = Y + (kk << 2) * VPAD + xcol;
                    dst[0 * VPAD] = val.x;
                    dst[1 * VPAD] = val.y;
                    dst[2 * VPAD] = val.z;
                    dst[3 * VPAD] = val.w;
                    // f += 128: q4 += 16 (mod 28), r += 4/5; hn carry into c
                    q4 += 16;
                    int rinc = 4;
                    if (q4 >= 28) { q4 -= 28; rinc = 5; }
                    hn += rinc;
                    if (hn >= 14) { hn -= 14; c++; }
                }
            }
        } else if (s >= 1) {
            // ================= COMPUTE tile tc from buffer grp ==========
            const int tc  = (t0 + s - 1) & 7;     // parity == grp
            const int rlo = TILE_U * tc, rhi = rlo + TILE_U;
            const uint32_t ybt = ybase + (uint32_t)(grp * (8 * VPAD) * 4);
            #pragma unroll
            for (int i = 0; i < 13; i++) {
                int jl = 4 * i + wg;
                if (jl < 49) {
                    const int ulo = 768 * jl, uhi = ulo + 768;
                    if (ulo < rhi && uhi > rlo) {
                        int clo = max(ulo, rlo);
                        int chi = min(uhi, rhi);
                        int u   = clo + 4 * lane;
                        if (u < chi) {
                            int sp = (unsigned)u / 588u;
                            int v  = u - sp * 588;
                            int rl = sp - 8 * tc;         // 0..7
                            uint32_t ya = ybt + 4u * (rl * VPAD
                                         + ((((v >> 2) ^ (rl >> 2)) << 2) | (v & 3)));
                            uint32_t wa = wbase + 4u * (u - ulo);
                            unsigned long long p01 = 0, p23 = 0;
                            while (u < chi) {
                                unsigned long long y01, y23, w01, w23;
                                asm volatile("ld.shared.v2.b64 {%0,%1}, [%2];"
                                             : "=l"(y01), "=l"(y23) : "r"(ya));
                                asm volatile("ld.shared.v2.b64 {%0,%1}, [%2];"
                                             : "=l"(w01), "=l"(w23) : "r"(wa));
                                asm volatile("fma.rn.f32x2 %0, %1, %2, %0;"
                                             : "+l"(p01) : "l"(y01), "l"(w01));
                                asm volatile("fma.rn.f32x2 %0, %1, %2, %0;"
                                             : "+l"(p23) : "l"(y23), "l"(w23));
                                u  += 128;        // 32 lanes * 4 floats
                                wa += 512;
                                v  += 128;
                                if (v >= 588) {   // row wrap: re-derive address
                                    v -= 588; rl++;
                                    ya = ybt + 4u * (rl * VPAD
                                         + ((((v >> 2) ^ (rl >> 2)) << 2) | (v & 3)));
                                } else {
                                    ya += 512;
                                }
                            }
                            acc[i] += (__uint_as_float((uint32_t)p01)
                                     + __uint_as_float((uint32_t)(p01 >> 32)))
                                    + (__uint_as_float((uint32_t)p23)
                                     + __uint_as_float((uint32_t)(p23 >> 32)));
                        }
                    }
                }
            }
        }
        __syncthreads();   // antiphase pacing + buffer-reuse protection
    }

    // ---- merge both groups' row partials ----
    #pragma unroll
    for (int i = 0; i < 13; i++) {
        int jl = 4 * i + wg;
        if (jl < 49) {
            float a = acc[i];
            #pragma unroll
            for (int off = 16; off; off >>= 1)
                a += __shfl_xor_sync(0xffffffffu, a, off);
            if (lane == 0 && a != 0.f)
                atomicAdd(&outacc[jl], a);
        }
    }
    __syncthreads();

    if (tid < 49)
        out[b * 196 + 49 * g + tid] = outacc[tid] + __ldg(bias);
}

extern "C" void kernel_launch(void* const* d_in, const int* in_sizes, int n_in,
                              void* d_out, int out_size)
{
    const float* x  = (const float*)d_in[0];
    const float* W  = (const float*)d_in[1];
    const float* bb = (const float*)d_in[2];
    float* out = (float*)d_out;

    const int smem_bytes = (16 * VPAD + 768 + 64) * sizeof(float);  // ~42 KB
    cudaFuncSetAttribute(patch_scorer_v13,
                         cudaFuncAttributeMaxDynamicSharedMemorySize, smem_bytes);

    patch_scorer_v13<<<512 * 4, THREADS, smem_bytes>>>(x, W, bb, out);
}

// round 16
// speedup vs baseline: 1.2474x; 1.2474x over previous
#include <cuda_runtime.h>
#include <cstdint>

// SimplePatchScorer: out[b, j] = dot(W, permuted_patch_row(b, j)) + bias
//   x: (512, 3, 224, 224) fp32, W: (1,768), b: (1,) -> out: (512, 196)
//
// flat[u], u = s*588 + v; s = ph*16+pw; v = c*196 + hn*14 + wn.
// out[b,j] = sum_t W[t]*flat[768j+t] + bias.
// lcm(588,768)=37632 => 4 groups/image: s in [64g,64g+64), j in [49g,49g+49).
//
// v14 = v9 config (quarter tiles 16 s' rows, 256 thr, 5 CTAs/SM, 4-way
// stagger, f32x2 smem dot) with BRANCH-FREE phase 2:
//  - no XOR swizzle -> row-wrap becomes a select (ya += 512 + wrap*64),
//    eliminating the per-lane divergent rederive branch of v9,
//  - full rows (46/49) fully unrolled to their exact 6 iterations
//    (uniform trip count) -> no loop branch, better LDS scheduling,
//  - straddle rows (j=12,24,36) keep a short select-wrap while loop.

#define VPAD      604          // mult of 4; VPAD-588 = 16 (wrap pad skip)
#define QUARTER_U 9408         // 16 * 588
#define THREADS   256

__global__ __launch_bounds__(THREADS, 5)
void patch_scorer_v14(const float* __restrict__ x,
                      const float* __restrict__ W,
                      const float* __restrict__ bias,
                      float* __restrict__ out)
{
    extern __shared__ float smem[];
    float* Y  = smem;               // [16][604]
    float* Ws = smem + 16 * VPAD;   // [768]

    const int tid  = threadIdx.x;
    const int g    = blockIdx.x & 3;
    const int b    = blockIdx.x >> 2;
    const int lane = tid & 31;
    const int warp = tid >> 5;      // 8 warps

    const float* xb = x + (size_t)b * 150528;
    const uint32_t ybase = (uint32_t)__cvta_generic_to_shared(Y);
    const uint32_t wbase = (uint32_t)__cvta_generic_to_shared(Ws);

    if (tid < 192)                  // 192 float4 = 768 floats
        ((float4*)Ws)[tid] = ((const float4*)W)[tid];
    // visible after the first phase-1 __syncthreads

    float acc[7];
    #pragma unroll
    for (int i = 0; i < 7; i++) acc[i] = 0.f;

    const int q0 = (blockIdx.x >> 2) & 3;   // stagger start quarter

    for (int qq = 0; qq < 4; qq++) {
        const int q = (q0 + qq) & 3;
        if (qq) __syncthreads();    // previous compute done before overwrite

        // ---- Phase 1: stream quarter q's region -> smem tile ----
        // ph = 4g + q; 42 rows x 56 float4 = 2352 float4 over 256 threads.
        {
            const int hoff = 4 * g + q;
            int w4 = tid % 56;
            int r  = tid / 56;
            int hn = r % 14;
            int c  = r / 14;
            #pragma unroll 2
            for (int e4 = tid; e4 < 2352; e4 += THREADS) {
                int w = w4 << 2;
                float4 val = __ldcs((const float4*)(xb +
                    (size_t)c * 50176 + (hn * 16 + hoff) * 224 + w));

                int pw = w & 15;                // 0,4,8,12
                int wn = w >> 4;
                float* dst = &Y[pw * VPAD + c * 196 + hn * 14 + wn];
                dst[0 * VPAD] = val.x;
                dst[1 * VPAD] = val.y;
                dst[2 * VPAD] = val.z;
                dst[3 * VPAD] = val.w;

                w4 += 32;                       // e4 += 256 carry chain
                int rinc = 4;
                if (w4 >= 56) { w4 -= 56; rinc = 5; }
                hn += rinc;
                if (hn >= 14) { hn -= 14; c++; }
            }
        }
        __syncthreads();

        // ---- Phase 2: branch-free f32x2 dot over [9408q, 9408q+9408) ----
        const int rlo = QUARTER_U * q, rhi = rlo + QUARTER_U;
        #pragma unroll
        for (int i = 0; i < 7; i++) {
            int jl = warp + 8 * i;
            if (jl >= 49) continue;
            const int ulo = 768 * jl, uhi = ulo + 768;
            if (ulo >= rhi || uhi <= rlo) continue;   // row not in this tile

            if (ulo >= rlo && uhi <= rhi) {
                // ===== full row: exactly 6 iterations, no branches =====
                int u0 = ulo + 4 * lane;
                int sp = (unsigned)u0 / 588u;         // one div per row
                int v  = u0 - sp * 588;
                uint32_t ya = ybase + 4u * ((sp - 16 * q) * VPAD + v);
                uint32_t wa = wbase + 4u * (4 * lane);
                unsigned long long p01 = 0, p23 = 0;
                #pragma unroll
                for (int k = 0; k < 6; k++) {
                    unsigned long long y01, y23, w01, w23;
                    asm volatile("ld.shared.v2.b64 {%0,%1}, [%2];"
                                 : "=l"(y01), "=l"(y23) : "r"(ya));
                    asm volatile("ld.shared.v2.b64 {%0,%1}, [%2];"
                                 : "=l"(w01), "=l"(w23) : "r"(wa));
                    asm volatile("fma.rn.f32x2 %0, %1, %2, %0;"
                                 : "+l"(p01) : "l"(y01), "l"(w01));
                    asm volatile("fma.rn.f32x2 %0, %1, %2, %0;"
                                 : "+l"(p23) : "l"(y23), "l"(w23));
                    if (k < 5) {
                        v += 128;
                        bool wrap = (v >= 588);       // select, not branch
                        v  -= wrap ? 588 : 0;
                        ya += wrap ? 576 : 512;       // 512 + 16-float pad skip
                        wa += 512;
                    }
                }
                acc[i] += (__uint_as_float((uint32_t)p01)
                         + __uint_as_float((uint32_t)(p01 >> 32)))
                        + (__uint_as_float((uint32_t)p23)
                         + __uint_as_float((uint32_t)(p23 >> 32)));
            } else {
                // ===== straddle row (j = 12, 24, 36): select-wrap loop =====
                int clo = max(ulo, rlo);
                int chi = min(uhi, rhi);
                int u   = clo + 4 * lane;
                if (u < chi) {
                    int sp = (unsigned)u / 588u;
                    int v  = u - sp * 588;
                    uint32_t ya = ybase + 4u * ((sp - 16 * q) * VPAD + v);
                    uint32_t wa = wbase + 4u * (u - ulo);
                    unsigned long long p01 = 0, p23 = 0;
                    while (u < chi) {
                        unsigned long long y01, y23, w01, w23;
                        asm volatile("ld.shared.v2.b64 {%0,%1}, [%2];"
                                     : "=l"(y01), "=l"(y23) : "r"(ya));
                        asm volatile("ld.shared.v2.b64 {%0,%1}, [%2];"
                                     : "=l"(w01), "=l"(w23) : "r"(wa));
                        asm volatile("fma.rn.f32x2 %0, %1, %2, %0;"
                                     : "+l"(p01) : "l"(y01), "l"(w01));
                        asm volatile("fma.rn.f32x2 %0, %1, %2, %0;"
                                     : "+l"(p23) : "l"(y23), "l"(w23));
                        u  += 128;
                        wa += 512;
                        v  += 128;
                        bool wrap = (v >= 588);
                        v  -= wrap ? 588 : 0;
                        ya += wrap ? 576 : 512;
                    }
                    acc[i] += (__uint_as_float((uint32_t)p01)
                             + __uint_as_float((uint32_t)(p01 >> 32)))
                            + (__uint_as_float((uint32_t)p23)
                             + __uint_as_float((uint32_t)(p23 >> 32)));
                }
            }
        }
    }

    // ---- final warp reductions + store ----
    const float bv = __ldg(bias);
    #pragma unroll
    for (int i = 0; i < 7; i++) {
        int jl = warp + 8 * i;
        if (jl < 49) {
            float a = acc[i];
            #pragma unroll
            for (int off = 16; off; off >>= 1)
                a += __shfl_xor_sync(0xffffffffu, a, off);
            if (lane == 0)
                out[b * 196 + 49 * g + jl] = a + bv;
        }
    }
}

extern "C" void kernel_launch(void* const* d_in, const int* in_sizes, int n_in,
                              void* d_out, int out_size)
{
    const float* x  = (const float*)d_in[0];
    const float* W  = (const float*)d_in[1];
    const float* bb = (const float*)d_in[2];
    float* out = (float*)d_out;

    const int smem_bytes = (16 * VPAD + 768) * sizeof(float);  // ~40.8 KB
    cudaFuncSetAttribute(patch_scorer_v14,
                         cudaFuncAttributeMaxDynamicSharedMemorySize, smem_bytes);

    patch_scorer_v14<<<512 * 4, THREADS, smem_bytes>>>(x, W, bb, out);
}

// round 17
// speedup vs baseline: 1.3973x; 1.1202x over previous
#include <cuda_runtime.h>
#include <cstdint>

// SimplePatchScorer: out[b, j] = dot(W, permuted_patch_row(b, j)) + bias
//   x: (512, 3, 224, 224) fp32, W: (1,768), b: (1,) -> out: (512, 196)
//
// flat[u], u = s*588 + v; s = ph*16+pw; v = c*196 + hn*14 + wn.
// out[b,j] = sum_t W[t]*flat[768j+t] + bias.
// lcm(588,768)=37632 => 4 groups/image: s in [64g,64g+64), j in [49g,49g+49).
//
// v15 = v9 (quarter tiles 16 s' rows, XOR-swizzled smem, f32x2 smem dot,
// 4-way CTA stagger) at 512 THREADS / 3 CTAs/SM:
//   48 warps/SM (75% occ, vs v9's 40), 2x phase-1 load parallelism per CTA,
//   ~3 rows per warp in phase 2 (shorter serial chains). Per-element code
//   identical to v9 (best measured mix).

#define VPAD      604          // mult of 4; 151 granules per row
#define QUARTER_U 9408         // 16 * 588
#define THREADS   512

__global__ __launch_bounds__(THREADS, 3)
void patch_scorer_v15(const float* __restrict__ x,
                      const float* __restrict__ W,
                      const float* __restrict__ bias,
                      float* __restrict__ out)
{
    extern __shared__ float smem[];
    float* Y  = smem;               // [16][604], XOR-swizzled granules
    float* Ws = smem + 16 * VPAD;   // [768]

    const int tid  = threadIdx.x;
    const int g    = blockIdx.x & 3;
    const int b    = blockIdx.x >> 2;
    const int lane = tid & 31;
    const int warp = tid >> 5;      // 16 warps

    const float* xb = x + (size_t)b * 150528;
    const uint32_t ybase = (uint32_t)__cvta_generic_to_shared(Y);
    const uint32_t wbase = (uint32_t)__cvta_generic_to_shared(Ws);

    if (tid < 192)                  // 192 float4 = 768 floats
        ((float4*)Ws)[tid] = ((const float4*)W)[tid];
    // visible after the first phase-1 __syncthreads

    float acc[4];
    #pragma unroll
    for (int i = 0; i < 4; i++) acc[i] = 0.f;

    const int q0 = (blockIdx.x >> 2) & 3;   // stagger start quarter

    for (int qq = 0; qq < 4; qq++) {
        const int q = (q0 + qq) & 3;
        if (qq) __syncthreads();    // previous compute done before overwrite

        // ---- Phase 1: stream quarter q's region -> swizzled smem tile ----
        // ph = 4g + q; 42 rows x 56 float4 = 2352 float4 over 512 threads.
        {
            const int hoff = 4 * g + q;
            int w4 = tid % 56;
            int r  = tid / 56;      // 0..9 at start
            int hn = r % 14;
            int c  = r / 14;        // 0 at start
            #pragma unroll 2
            for (int e4 = tid; e4 < 2352; e4 += THREADS) {
                int w = w4 << 2;
                float4 val = __ldcs((const float4*)(xb +
                    (size_t)c * 50176 + (hn * 16 + hoff) * 224 + w));

                int pw  = w & 15;               // 0,4,8,12
                int wn  = w >> 4;
                int col = c * 196 + hn * 14 + wn;
                // swizzled column: granule ^ (row>>2); row>>2 == pw>>2 for e=0..3
                int xcol = ((((col >> 2) ^ (pw >> 2)) << 2)) | (col & 3);
                float* dst = Y + pw * VPAD + xcol;
                dst[0 * VPAD] = val.x;
                dst[1 * VPAD] = val.y;
                dst[2 * VPAD] = val.z;
                dst[3 * VPAD] = val.w;

                // e4 += 512: w4 += 8 (mod 56), r += 9/10; hn carry into c
                w4 += 8;
                int rinc = 9;
                if (w4 >= 56) { w4 -= 56; rinc = 10; }
                hn += rinc;
                if (hn >= 14) { hn -= 14; c++; }
            }
        }
        __syncthreads();

        // ---- Phase 2: swizzled f32x2 dot over u' in [9408q, 9408q+9408) ----
        const int rlo = QUARTER_U * q, rhi = rlo + QUARTER_U;
        #pragma unroll
        for (int i = 0; i < 4; i++) {
            int jl = warp + 16 * i;
            if (jl < 49) {
                int ulo = max(768 * jl, rlo);
                int uhi = min(768 * jl + 768, rhi);
                int u   = ulo + 4 * lane;
                if (u < uhi) {
                    int sp = (unsigned)u / 588u;          // one div per segment
                    int v  = u - sp * 588;
                    int rl = sp - 16 * q;                 // local row 0..15
                    uint32_t ya = ybase + 4u * (rl * VPAD
                                 + ((((v >> 2) ^ (rl >> 2)) << 2) | (v & 3)));
                    uint32_t wa = wbase + 4u * (u - 768 * jl);
                    unsigned long long p01 = 0, p23 = 0;
                    while (u < uhi) {
                        unsigned long long y01, y23, w01, w23;
                        asm volatile("ld.shared.v2.b64 {%0,%1}, [%2];"
                                     : "=l"(y01), "=l"(y23) : "r"(ya));
                        asm volatile("ld.shared.v2.b64 {%0,%1}, [%2];"
                                     : "=l"(w01), "=l"(w23) : "r"(wa));
                        asm volatile("fma.rn.f32x2 %0, %1, %2, %0;"
                                     : "+l"(p01) : "l"(y01), "l"(w01));
                        asm volatile("fma.rn.f32x2 %0, %1, %2, %0;"
                                     : "+l"(p23) : "l"(y23), "l"(w23));
                        u  += 128;            // 32 lanes * 4 floats
                        wa += 512;
                        v  += 128;
                        if (v >= 588) {       // row wrap: re-derive swizzled addr
                            v -= 588; rl++;
                            ya = ybase + 4u * (rl * VPAD
                                 + ((((v >> 2) ^ (rl >> 2)) << 2) | (v & 3)));
                        } else {
                            ya += 512;        // +32 granules; low bits safe
                        }
                    }
                    acc[i] += (__uint_as_float((uint32_t)p01)
                             + __uint_as_float((uint32_t)(p01 >> 32)))
                            + (__uint_as_float((uint32_t)p23)
                             + __uint_as_float((uint32_t)(p23 >> 32)));
                }
            }
        }
    }

    // ---- final warp reductions + store ----
    const float bv = __ldg(bias);
    #pragma unroll
    for (int i = 0; i < 4; i++) {
        int jl = warp + 16 * i;
        if (jl < 49) {
            float a = acc[i];
            #pragma unroll
            for (int off = 16; off; off >>= 1)
                a += __shfl_xor_sync(0xffffffffu, a, off);
            if (lane == 0)
                out[b * 196 + 49 * g + jl] = a + bv;
        }
    }
}

extern "C" void kernel_launch(void* const* d_in, const int* in_sizes, int n_in,
                              void* d_out, int out_size)
{
    const float* x  = (const float*)d_in[0];
    const float* W  = (const float*)d_in[1];
    const float* bb = (const float*)d_in[2];
    float* out = (float*)d_out;

    const int smem_bytes = (16 * VPAD + 768) * sizeof(float);  // ~40.8 KB
    cudaFuncSetAttribute(patch_scorer_v15,
                         cudaFuncAttributeMaxDynamicSharedMemorySize, smem_bytes);

    patch_scorer_v15<<<512 * 4, THREADS, smem_bytes>>>(x, W, bb, out);
}